// round 10
// baseline (speedup 1.0000x reference)
#include <cuda_runtime.h>
#include <math.h>

#define BB 8
#define CC 64
#define NN 2048
#define KK 32
#define BN (BB*NN)        // 16384 points

// ---------------- device scratch (no allocations allowed) ----------------
__device__ float g_xx[BN];
__device__ int   g_idx[BN*KK];
__device__ unsigned g_keys[(size_t)BN*NN];   // per-query distance keys (134MB)
__device__ float g_WT [3*CC*CC];   // Wq/Wk/Wv transposed: [w][cin][cout]
__device__ float g_W1T[CC*128];    // [cin][cout]
__device__ float g_W2T[128*CC];    // [cin][cout]
__device__ float g_q [BN*CC];      // point-major [bn][c]
__device__ float g_yk[BN*CC];
__device__ float g_yv[BN*CC];
__device__ float g_s1[BN*CC];      // x + attn_out (pre-BN1), point-major
__device__ float g_x1[BN*CC];      // BN1 output, point-major
__device__ float g_h [BN*128];     // lrelu(W1@x1), point-major
__device__ float g_s2[BN*CC];      // x1 + ff (pre-BN2), point-major
__device__ float g_ps[2][CC*16*2]; // stats partials
__device__ float g_mean1[CC], g_rstd1[CC], g_mean2[CC], g_rstd2[CC];

// packed fp32x2 FMA (Blackwell FFMA2): d = a*b + c on both lanes
#define FMA_F32X2(d, a, b, c) \
    asm("fma.rn.f32x2 %0, %1, %2, %3;" : "=l"(d) : "l"(a), "l"(b), "l"(c))

// order-preserving float -> uint32 key
__device__ __forceinline__ unsigned fkey(float f) {
    unsigned b = __float_as_uint(f);
    return b ^ ((unsigned)((int)b >> 31) | 0x80000000u);
}

// ---------------- 0) transpose weights ----------------
__global__ void k_prep(const float* __restrict__ Wq, const float* __restrict__ Wk,
                       const float* __restrict__ Wv, const float* __restrict__ W1,
                       const float* __restrict__ W2) {
    int i = blockIdx.x * 256 + threadIdx.x;
    if (i < CC*CC) {
        int o = i >> 6, ci = i & 63;
        g_WT[0*CC*CC + ci*CC + o] = Wq[i];
        g_WT[1*CC*CC + ci*CC + o] = Wk[i];
        g_WT[2*CC*CC + ci*CC + o] = Wv[i];
    }
    if (i < 128*CC) {
        int o = i >> 6, ci = i & 63;      // W1[o][ci], o<128
        g_W1T[ci*128 + o] = W1[i];
        int co = i >> 7, k2 = i & 127;    // W2[co][k2], co<64
        g_W2T[k2*CC + co] = W2[i];
    }
}

// ---------------- 1) per-point squared norms ----------------
__global__ void k_xx(const float* __restrict__ x) {
    int b = blockIdx.y;
    int n = blockIdx.x * 256 + threadIdx.x;
    const float* xb = x + b*CC*NN;
    float s = 0.f;
#pragma unroll
    for (int c = 0; c < CC; c++) { float v = xb[c*NN + n]; s = fmaf(v, v, s); }
    g_xx[b*NN + n] = s;
}

// ---------------- 2a) distance keys: pure GEMM, no selection ----------------
// 128 threads (thread = query), grid (NN/128, BB, 4). Each block: 128 queries
// x 512 candidates. Keys staged in smem, cooperatively stored coalesced.
#define CPAD 68

__global__ __launch_bounds__(128, 4) void k_dist(const float* __restrict__ x) {
    __shared__ __align__(16) float sh_c[32*CPAD];      // [m][c] candidate tile
    __shared__ float sh_xx[32];
    __shared__ __align__(16) unsigned sh_k[128*36];    // [q][m] key staging (18KB)

    int tid = threadIdx.x;
    int b   = blockIdx.y;
    int n   = blockIdx.x * 128 + tid;
    const float* xb = x + b*CC*NN;

    // query as packed channel pairs (q[2k], q[2k+1])
    unsigned long long qp[32];
#pragma unroll
    for (int k = 0; k < 32; k++) {
        float f0 = xb[(2*k  )*NN + n];
        float f1 = xb[(2*k+1)*NN + n];
        asm("mov.b64 %0, {%1, %2};" : "=l"(qp[k]) : "f"(f0), "f"(f1));
    }
    float xxn = g_xx[b*NN + n];

#pragma unroll 1
    for (int t = 0; t < 16; t++) {
        int m0 = blockIdx.z * 512 + t * 32;
        __syncthreads();
        for (int i = tid; i < 32*CC; i += 128) {
            int m = i & 31, c = i >> 5;
            sh_c[m*CPAD + c] = xb[c*NN + m0 + m];
        }
        if (tid < 32) sh_xx[tid] = g_xx[b*NN + m0 + tid];
        __syncthreads();

#pragma unroll 1
        for (int m4 = 0; m4 < 8; m4++) {
            unsigned long long acc[4] = {0ull, 0ull, 0ull, 0ull};
#pragma unroll
            for (int c4 = 0; c4 < 16; c4++) {
#pragma unroll
                for (int j = 0; j < 4; j++) {
                    ulonglong2 s = *(const ulonglong2*)&sh_c[(m4*4+j)*CPAD + c4*4];
                    FMA_F32X2(acc[j], qp[2*c4],   s.x, acc[j]);
                    FMA_F32X2(acc[j], qp[2*c4+1], s.y, acc[j]);
                }
            }
            unsigned kq[4];
#pragma unroll
            for (int j = 0; j < 4; j++) {
                float lo, hi;
                asm("mov.b64 {%0, %1}, %2;" : "=f"(lo), "=f"(hi) : "l"(acc[j]));
                float a   = lo + hi;
                float val = fmaf(2.f, a, -xxn) - sh_xx[m4*4 + j];
                kq[j] = fkey(val);
            }
            *reinterpret_cast<uint4*>(&sh_k[tid*36 + m4*4]) =
                make_uint4(kq[0], kq[1], kq[2], kq[3]);
        }
        __syncthreads();

        // cooperative coalesced store: 128 rows x 32 keys = 1024 uint4
#pragma unroll
        for (int k = 0; k < 8; k++) {
            int e  = k*128 + tid;
            int q  = e >> 3, jj = e & 7;
            size_t row = (size_t)(b*NN + blockIdx.x*128 + q);
            *reinterpret_cast<uint4*>(g_keys + row*NN + m0 + jj*4) =
                *reinterpret_cast<const uint4*>(&sh_k[q*36 + jj*4]);
        }
    }
}

// ---------------- 2b) top-32 selection: warp per query, register-only ----------------
// Lane holds 64 keys; sorted per-lane top-4; 32 warp-argmax extraction rounds;
// rare rescan when a lane contributes >4. Entry (key<<32)|(2047-m): total order,
// ties -> lower index (matches stable top_k).
__global__ __launch_bounds__(256) void k_sel() {
    int tid = threadIdx.x, wid = tid >> 5, lane = tid & 31;
    int bn = blockIdx.x * 8 + wid;
    const uint4* src = reinterpret_cast<const uint4*>(g_keys + (size_t)bn*NN);

    uint4 k4[16];
#pragma unroll
    for (int i = 0; i < 16; i++) k4[i] = src[i*32 + lane];

    unsigned long long l0 = 0, l1 = 0, l2 = 0, l3 = 0;
#pragma unroll
    for (int i = 0; i < 16; i++) {
        int mb = (i*32 + lane)*4;
        unsigned kk[4] = {k4[i].x, k4[i].y, k4[i].z, k4[i].w};
#pragma unroll
        for (int j = 0; j < 4; j++) {
            unsigned long long e =
                ((unsigned long long)kk[j] << 32) | (unsigned)(2047 - (mb + j));
            if (e > l3) {
                if (e > l0)      { l3 = l2; l2 = l1; l1 = l0; l0 = e; }
                else if (e > l1) { l3 = l2; l2 = l1; l1 = e; }
                else if (e > l2) { l3 = l2; l2 = e; }
                else             { l3 = e; }
            }
        }
    }

    unsigned long long head = l0;
    int ptr = 0;
    int* op = g_idx + bn*KK;
#pragma unroll 1
    for (int r = 0; r < KK; r++) {
        unsigned long long wm = head;
#pragma unroll
        for (int o = 16; o > 0; o >>= 1) {
            unsigned long long t = __shfl_xor_sync(0xffffffffu, wm, o);
            wm = t > wm ? t : wm;
        }
        if (head == wm) {            // unique owner (entries unique)
            ptr++;
            if      (ptr == 1) head = l1;
            else if (ptr == 2) head = l2;
            else if (ptr == 3) head = l3;
            else {
                // rescan this lane's 64 keys for best entry strictly below wm
                unsigned long long best = 0;
#pragma unroll
                for (int i = 0; i < 16; i++) {
                    int mb = (i*32 + lane)*4;
                    unsigned kk[4] = {k4[i].x, k4[i].y, k4[i].z, k4[i].w};
#pragma unroll
                    for (int j = 0; j < 4; j++) {
                        unsigned long long e =
                            ((unsigned long long)kk[j] << 32) | (unsigned)(2047 - (mb + j));
                        if (e < wm && e > best) best = e;
                    }
                }
                head = best;
            }
        }
        if (lane == r) op[r] = 2047 - (int)((unsigned)wm & 0x7FFu);
    }
}

// ---------------- 3) projections q/yk/yv = W @ x (w = blockIdx.z) ----------------
__global__ void k_proj(const float* __restrict__ x) {
    __shared__ float shx[CC*64];   // [c][p]
    __shared__ float shW[CC*CC];   // [cin][cout]
    int b  = blockIdx.y;
    int w  = blockIdx.z;
    int n0 = blockIdx.x * 64;
    int tid = threadIdx.x;
    const float* xb = x + b*CC*NN;
    for (int i = tid; i < CC*64; i += 256) {
        int c = i >> 6, p = i & 63;
        shx[c*64 + p] = xb[c*NN + n0 + p];
    }
    for (int i = tid; i < CC*CC; i += 256) shW[i] = g_WT[w*CC*CC + i];
    __syncthreads();

    int p  = tid & 63;
    int cg = (tid >> 6) << 4;           // 16 output channels per thread
    int bn = b*NN + n0 + p;
    float4 acc[4];
#pragma unroll
    for (int g = 0; g < 4; g++) acc[g] = make_float4(0.f, 0.f, 0.f, 0.f);
#pragma unroll
    for (int k = 0; k < CC; k++) {
        float xv = shx[k*64 + p];
#pragma unroll
        for (int g = 0; g < 4; g++) {
            float4 wv = *(const float4*)&shW[k*CC + cg + g*4];
            acc[g].x = fmaf(xv, wv.x, acc[g].x);
            acc[g].y = fmaf(xv, wv.y, acc[g].y);
            acc[g].z = fmaf(xv, wv.z, acc[g].z);
            acc[g].w = fmaf(xv, wv.w, acc[g].w);
        }
    }
    float* dst = (w == 0 ? g_q : (w == 1 ? g_yk : g_yv)) + bn*CC + cg;
#pragma unroll
    for (int g = 0; g < 4; g++) *(float4*)&dst[g*4] = acc[g];
}

// ---------------- 4) attention (warp per point) + residual -> s1 ----------------
__global__ void k_attn(const float* __restrict__ x) {
    __shared__ float qsh[8][64];
    __shared__ float ykn[8][64];
    __shared__ float att[8][KK*8];
    __shared__ int   nid[8][KK];
    int tid  = threadIdx.x;
    int wid  = tid >> 5, lane = tid & 31;
    int bn   = blockIdx.x * 8 + wid;
    int b    = bn >> 11;
    int n    = bn & (NN - 1);

    qsh[wid][lane]      = g_q [bn*CC + lane];
    qsh[wid][lane + 32] = g_q [bn*CC + lane + 32];
    ykn[wid][lane]      = g_yk[bn*CC + lane];
    ykn[wid][lane + 32] = g_yk[bn*CC + lane + 32];
    int gn = b*NN + g_idx[bn*KK + lane];   // global row of this lane's neighbor
    nid[wid][lane] = gn;
    __syncwarp();

    const float4* kr = (const float4*)&g_yk[gn*CC];
    float e[8];
#pragma unroll
    for (int h = 0; h < 8; h++) e[h] = 0.f;
#pragma unroll
    for (int c4 = 0; c4 < 16; c4++) {
        float4 kv = kr[c4];
        int c = c4*4, h = c4 >> 1;
        float t = (kv.x - ykn[wid][c+0]) * qsh[wid][c+0];
        t = fmaf(kv.y - ykn[wid][c+1], qsh[wid][c+1], t);
        t = fmaf(kv.z - ykn[wid][c+2], qsh[wid][c+2], t);
        t = fmaf(kv.w - ykn[wid][c+3], qsh[wid][c+3], t);
        e[h] += t;
    }
    const float sc = 0.3535533905932738f;  // 1/sqrt(8)
#pragma unroll
    for (int h = 0; h < 8; h++) {
        float eh = e[h] * sc;
        float mx = eh;
#pragma unroll
        for (int o = 16; o > 0; o >>= 1) mx = fmaxf(mx, __shfl_xor_sync(0xffffffffu, mx, o));
        float ex = __expf(eh - mx);
        float sm = ex;
#pragma unroll
        for (int o = 16; o > 0; o >>= 1) sm += __shfl_xor_sync(0xffffffffu, sm, o);
        att[wid][lane*8 + h] = ex / sm;
    }
    __syncwarp();

    // out[c] = sum_j a[j][c>>3]*yv_j[c] - yv_center[c]  (softmax sums to 1)
    float acc0 = 0.f, acc1 = 0.f;
    int h0 = lane >> 3, h1 = (lane >> 3) + 4;
#pragma unroll 4
    for (int j = 0; j < KK; j++) {
        const float* vr = &g_yv[nid[wid][j]*CC];
        acc0 = fmaf(att[wid][j*8 + h0], vr[lane],      acc0);
        acc1 = fmaf(att[wid][j*8 + h1], vr[lane + 32], acc1);
    }
    acc0 -= g_yv[bn*CC + lane];
    acc1 -= g_yv[bn*CC + lane + 32];

    const float* xb = x + b*CC*NN;
    g_s1[bn*CC + lane]      = xb[lane*NN + n]        + acc0;
    g_s1[bn*CC + lane + 32] = xb[(lane + 32)*NN + n] + acc1;
}

// ---------------- 5a/8a) BN stats partials: grid (CC, 16) ----------------
__global__ void k_statsA(int which) {
    const float* s = which ? g_s2 : g_s1;
    int c = blockIdx.x, chunk = blockIdx.y, tid = threadIdx.x;
    int r0 = chunk * 1024;
    float sum = 0.f, sq = 0.f;
#pragma unroll
    for (int r = 0; r < 1024; r += 256) {
        float v = s[(r0 + r + tid)*CC + c];
        sum += v; sq = fmaf(v, v, sq);
    }
    __shared__ float ss[256], s2[256];
    ss[tid] = sum; s2[tid] = sq;
    __syncthreads();
    for (int st = 128; st > 0; st >>= 1) {
        if (tid < st) { ss[tid] += ss[tid + st]; s2[tid] += s2[tid + st]; }
        __syncthreads();
    }
    if (tid == 0) {
        g_ps[which][(c*16 + chunk)*2    ] = ss[0];
        g_ps[which][(c*16 + chunk)*2 + 1] = s2[0];
    }
}

// ---------------- 5b/8b) BN stats finalize ----------------
__global__ void k_statsB(int which) {
    int c = threadIdx.x;
    float sum = 0.f, sq = 0.f;
#pragma unroll
    for (int k = 0; k < 16; k++) {
        sum += g_ps[which][(c*16 + k)*2];
        sq  += g_ps[which][(c*16 + k)*2 + 1];
    }
    float m   = sum * (1.f/BN);
    float var = sq  * (1.f/BN) - m*m;
    float r   = rsqrtf(var + 1e-5f);
    if (which) { g_mean2[c] = m; g_rstd2[c] = r; }
    else       { g_mean1[c] = m; g_rstd1[c] = r; }
}

// ---------------- 6) BN1 + h = lrelu(W1 @ x1); store x1, h ----------------
__global__ void k_ffn1(const float* __restrict__ gg1, const float* __restrict__ bb1) {
    __shared__ float x1sh[CC*32];   // [c][p], 8KB
    __shared__ float Wsh[CC*128];   // [cin][cout], 32KB
    int tid = threadIdx.x;
    int bn0 = blockIdx.x * 32;
    for (int i = tid; i < CC*128; i += 256) Wsh[i] = g_W1T[i];
    for (int i = tid; i < CC*32; i += 256) {
        int c = i >> 5, p = i & 31;
        float v = g_s1[(bn0 + p)*CC + c];
        float x1 = gg1[c]*(v - g_mean1[c])*g_rstd1[c] + bb1[c];
        x1sh[c*32 + p] = x1;
        g_x1[(bn0 + p)*CC + c] = x1;
    }
    __syncthreads();
    int p = tid & 31, og = (tid >> 5) * 16;
    float acc[16];
#pragma unroll
    for (int u = 0; u < 16; u++) acc[u] = 0.f;
#pragma unroll 8
    for (int k = 0; k < CC; k++) {
        float xv = x1sh[k*32 + p];
#pragma unroll
        for (int u = 0; u < 16; u++) acc[u] = fmaf(xv, Wsh[k*128 + og + u], acc[u]);
    }
    float* ho = g_h + (bn0 + p)*128 + og;
#pragma unroll
    for (int u4 = 0; u4 < 4; u4++) {
        float4 o;
        o.x = acc[u4*4+0] > 0.f ? acc[u4*4+0] : 0.2f*acc[u4*4+0];
        o.y = acc[u4*4+1] > 0.f ? acc[u4*4+1] : 0.2f*acc[u4*4+1];
        o.z = acc[u4*4+2] > 0.f ? acc[u4*4+2] : 0.2f*acc[u4*4+2];
        o.w = acc[u4*4+3] > 0.f ? acc[u4*4+3] : 0.2f*acc[u4*4+3];
        *(float4*)&ho[u4*4] = o;
    }
}

// ---------------- 7) s2 = x1 + W2 @ h ----------------
__global__ void k_ffn2() {
    __shared__ float hsh[128*16];   // [k][p], 8KB
    __shared__ float Wsh[128*CC];   // [k][cout], 32KB
    int tid = threadIdx.x;
    int bn0 = blockIdx.x * 16;
    for (int i = tid; i < 128*CC; i += 256) Wsh[i] = g_W2T[i];
    for (int i = tid; i < 128*16; i += 256) {
        int k = i >> 4, p = i & 15;
        hsh[k*16 + p] = g_h[(bn0 + p)*128 + k];
    }
    __syncthreads();
    int p = tid & 15, cg = (tid >> 4) * 4;
    float4 acc = make_float4(0.f, 0.f, 0.f, 0.f);
#pragma unroll 8
    for (int k = 0; k < 128; k++) {
        float hv = hsh[k*16 + p];
        float4 wv = *(const float4*)&Wsh[k*CC + cg];
        acc.x = fmaf(hv, wv.x, acc.x);
        acc.y = fmaf(hv, wv.y, acc.y);
        acc.z = fmaf(hv, wv.z, acc.z);
        acc.w = fmaf(hv, wv.w, acc.w);
    }
    int bn = bn0 + p;
    float4 x1v = *(const float4*)&g_x1[bn*CC + cg];
    float4 o;
    o.x = x1v.x + acc.x; o.y = x1v.y + acc.y;
    o.z = x1v.z + acc.z; o.w = x1v.w + acc.w;
    *(float4*)&g_s2[bn*CC + cg] = o;
}

// ---------------- 9) BN2 + transpose to (B, C, N) output ----------------
__global__ void k_final(const float* __restrict__ gg2, const float* __restrict__ bb2,
                        float* __restrict__ out) {
    int i = blockIdx.x * 256 + threadIdx.x;      // 0 .. B*C*N-1
    int n = i & (NN - 1);
    int c = (i >> 11) & 63;
    int b = i >> 17;
    float v = g_s2[(b*NN + n)*CC + c];
    out[i] = gg2[c]*(v - g_mean2[c])*g_rstd2[c] + bb2[c];
}

// ---------------- launcher ----------------
extern "C" void kernel_launch(void* const* d_in, const int* in_sizes, int n_in,
                              void* d_out, int out_size) {
    const float* x  = (const float*)d_in[0];
    const float* Wq = (const float*)d_in[1];
    const float* Wk = (const float*)d_in[2];
    const float* Wv = (const float*)d_in[3];
    const float* W1 = (const float*)d_in[4];
    const float* W2 = (const float*)d_in[5];
    const float* g1 = (const float*)d_in[6];
    const float* b1 = (const float*)d_in[7];
    const float* g2 = (const float*)d_in[8];
    const float* b2 = (const float*)d_in[9];
    float* out = (float*)d_out;

    k_prep  <<<32, 256>>>(Wq, Wk, Wv, W1, W2);
    k_xx    <<<dim3(NN/256, BB), 256>>>(x);
    k_dist  <<<dim3(NN/128, BB, 4), 128>>>(x);
    k_sel   <<<BN/8, 256>>>();
    k_proj  <<<dim3(NN/64, BB, 3), 256>>>(x);
    k_attn  <<<BN/8, 256>>>(x);
    k_statsA<<<dim3(CC, 16), 256>>>(0);
    k_statsB<<<1, 64>>>(0);
    k_ffn1  <<<BN/32, 256>>>(g1, b1);
    k_ffn2  <<<BN/16, 256>>>();
    k_statsA<<<dim3(CC, 16), 256>>>(1);
    k_statsB<<<1, 64>>>(1);
    k_final <<<(BB*CC*NN)/256, 256>>>(g2, b2, out);
}

// round 11
// speedup vs baseline: 1.2412x; 1.2412x over previous
#include <cuda_runtime.h>
#include <math.h>

#define BB 8
#define CC 64
#define NN 2048
#define KK 32
#define BN (BB*NN)        // 16384 points

// ---------------- device scratch (no allocations allowed) ----------------
__device__ float g_xx[BN];
__device__ int   g_idx[BN*KK];
__device__ unsigned g_keys[(size_t)BN*NN];   // per-query distance keys (134MB)
__device__ float g_WT [3*CC*CC];   // Wq/Wk/Wv transposed: [w][cin][cout]
__device__ float g_W1T[CC*128];    // [cin][cout]
__device__ float g_W2T[128*CC];    // [cin][cout]
__device__ float g_q [BN*CC];      // point-major [bn][c]
__device__ float g_yk[BN*CC];
__device__ float g_yv[BN*CC];
__device__ float g_s1[BN*CC];      // x + attn_out (pre-BN1), point-major
__device__ float g_x1[BN*CC];      // BN1 output, point-major
__device__ float g_h [BN*128];     // lrelu(W1@x1), point-major
__device__ float g_s2[BN*CC];      // x1 + ff (pre-BN2), point-major
__device__ float g_ps[2][CC*16*2]; // stats partials
__device__ float g_mean1[CC], g_rstd1[CC], g_mean2[CC], g_rstd2[CC];

// packed fp32x2 FMA (Blackwell FFMA2): d = a*b + c on both lanes
#define FMA_F32X2(d, a, b, c) \
    asm("fma.rn.f32x2 %0, %1, %2, %3;" : "=l"(d) : "l"(a), "l"(b), "l"(c))

// order-preserving float -> uint32 key
__device__ __forceinline__ unsigned fkey(float f) {
    unsigned b = __float_as_uint(f);
    return b ^ ((unsigned)((int)b >> 31) | 0x80000000u);
}

// ---------------- 0) transpose weights ----------------
__global__ void k_prep(const float* __restrict__ Wq, const float* __restrict__ Wk,
                       const float* __restrict__ Wv, const float* __restrict__ W1,
                       const float* __restrict__ W2) {
    int i = blockIdx.x * 256 + threadIdx.x;
    if (i < CC*CC) {
        int o = i >> 6, ci = i & 63;
        g_WT[0*CC*CC + ci*CC + o] = Wq[i];
        g_WT[1*CC*CC + ci*CC + o] = Wk[i];
        g_WT[2*CC*CC + ci*CC + o] = Wv[i];
    }
    if (i < 128*CC) {
        int o = i >> 6, ci = i & 63;      // W1[o][ci], o<128
        g_W1T[ci*128 + o] = W1[i];
        int co = i >> 7, k2 = i & 127;    // W2[co][k2], co<64
        g_W2T[k2*CC + co] = W2[i];
    }
}

// ---------------- 1) per-point squared norms ----------------
__global__ void k_xx(const float* __restrict__ x) {
    int b = blockIdx.y;
    int n = blockIdx.x * 256 + threadIdx.x;
    const float* xb = x + b*CC*NN;
    float s = 0.f;
#pragma unroll
    for (int c = 0; c < CC; c++) { float v = xb[c*NN + n]; s = fmaf(v, v, s); }
    g_xx[b*NN + n] = s;
}

// ---------------- 2a) distance keys: pure GEMM, no selection ----------------
// 128 threads (thread = query), grid (NN/128, BB, 4). Each block: 128 queries
// x 512 candidates. Keys staged in smem, cooperatively stored coalesced.
#define CPAD 68

__global__ __launch_bounds__(128, 4) void k_dist(const float* __restrict__ x) {
    __shared__ __align__(16) float sh_c[32*CPAD];      // [m][c] candidate tile
    __shared__ float sh_xx[32];
    __shared__ __align__(16) unsigned sh_k[128*36];    // [q][m] key staging (18KB)

    int tid = threadIdx.x;
    int b   = blockIdx.y;
    int n   = blockIdx.x * 128 + tid;
    const float* xb = x + b*CC*NN;

    // query as packed channel pairs (q[2k], q[2k+1])
    unsigned long long qp[32];
#pragma unroll
    for (int k = 0; k < 32; k++) {
        float f0 = xb[(2*k  )*NN + n];
        float f1 = xb[(2*k+1)*NN + n];
        asm("mov.b64 %0, {%1, %2};" : "=l"(qp[k]) : "f"(f0), "f"(f1));
    }
    float xxn = g_xx[b*NN + n];

#pragma unroll 1
    for (int t = 0; t < 16; t++) {
        int m0 = blockIdx.z * 512 + t * 32;
        __syncthreads();
        for (int i = tid; i < 32*CC; i += 128) {
            int m = i & 31, c = i >> 5;
            sh_c[m*CPAD + c] = xb[c*NN + m0 + m];
        }
        if (tid < 32) sh_xx[tid] = g_xx[b*NN + m0 + tid];
        __syncthreads();

#pragma unroll 1
        for (int m4 = 0; m4 < 8; m4++) {
            unsigned long long acc[4] = {0ull, 0ull, 0ull, 0ull};
#pragma unroll
            for (int c4 = 0; c4 < 16; c4++) {
#pragma unroll
                for (int j = 0; j < 4; j++) {
                    ulonglong2 s = *(const ulonglong2*)&sh_c[(m4*4+j)*CPAD + c4*4];
                    FMA_F32X2(acc[j], qp[2*c4],   s.x, acc[j]);
                    FMA_F32X2(acc[j], qp[2*c4+1], s.y, acc[j]);
                }
            }
            unsigned kq[4];
#pragma unroll
            for (int j = 0; j < 4; j++) {
                float lo, hi;
                asm("mov.b64 {%0, %1}, %2;" : "=f"(lo), "=f"(hi) : "l"(acc[j]));
                float a   = lo + hi;
                float val = fmaf(2.f, a, -xxn) - sh_xx[m4*4 + j];
                kq[j] = fkey(val);
            }
            *reinterpret_cast<uint4*>(&sh_k[tid*36 + m4*4]) =
                make_uint4(kq[0], kq[1], kq[2], kq[3]);
        }
        __syncthreads();

        // cooperative coalesced store: 128 rows x 32 keys = 1024 uint4
#pragma unroll
        for (int k = 0; k < 8; k++) {
            int e  = k*128 + tid;
            int q  = e >> 3, jj = e & 7;
            size_t row = (size_t)(b*NN + blockIdx.x*128 + q);
            *reinterpret_cast<uint4*>(g_keys + row*NN + m0 + jj*4) =
                *reinterpret_cast<const uint4*>(&sh_k[q*36 + jj*4]);
        }
    }
}

// ---------------- 2b) top-32 selection: warp per query, streaming regs ----------------
// Lane streams its 64 keys (16 uint4 loads, consumed immediately) into a sorted
// per-lane top-4; then 32 warp-argmax extraction rounds. The rare lane needing
// a 5th+ entry (P ~ 3e-4) rescans by RELOADING from global (L2-hot) instead of
// keeping keys register-resident. Entry (key<<32)|(2047-m): total order, ties ->
// lower index (matches stable top_k).
__global__ __launch_bounds__(256) void k_sel() {
    int tid = threadIdx.x, wid = tid >> 5, lane = tid & 31;
    int bn = blockIdx.x * 8 + wid;
    const uint4* src = reinterpret_cast<const uint4*>(g_keys + (size_t)bn*NN);

    unsigned long long l0 = 0, l1 = 0, l2 = 0, l3 = 0;
#pragma unroll 4
    for (int i = 0; i < 16; i++) {
        uint4 k4 = src[i*32 + lane];           // consumed immediately, not kept
        int mb = (i*32 + lane)*4;
        unsigned kk[4] = {k4.x, k4.y, k4.z, k4.w};
#pragma unroll
        for (int j = 0; j < 4; j++) {
            unsigned long long e =
                ((unsigned long long)kk[j] << 32) | (unsigned)(2047 - (mb + j));
            if (e > l3) {
                if (e > l0)      { l3 = l2; l2 = l1; l1 = l0; l0 = e; }
                else if (e > l1) { l3 = l2; l2 = l1; l1 = e; }
                else if (e > l2) { l3 = l2; l2 = e; }
                else             { l3 = e; }
            }
        }
    }

    unsigned long long head = l0;
    int ptr = 0;
    int* op = g_idx + bn*KK;
#pragma unroll 1
    for (int r = 0; r < KK; r++) {
        unsigned long long wm = head;
#pragma unroll
        for (int o = 16; o > 0; o >>= 1) {
            unsigned long long t = __shfl_xor_sync(0xffffffffu, wm, o);
            wm = t > wm ? t : wm;
        }
        if (head == wm) {            // unique owner (entries unique)
            ptr++;
            if      (ptr == 1) head = l1;
            else if (ptr == 2) head = l2;
            else if (ptr == 3) head = l3;
            else {
                // extremely rare: rescan this lane's 64 keys from global for the
                // best entry strictly below wm
                unsigned long long best = 0;
#pragma unroll 1
                for (int i = 0; i < 16; i++) {
                    uint4 k4 = src[i*32 + lane];
                    int mb = (i*32 + lane)*4;
                    unsigned kk[4] = {k4.x, k4.y, k4.z, k4.w};
#pragma unroll
                    for (int j = 0; j < 4; j++) {
                        unsigned long long e =
                            ((unsigned long long)kk[j] << 32) | (unsigned)(2047 - (mb + j));
                        if (e < wm && e > best) best = e;
                    }
                }
                head = best;
            }
        }
        if (lane == r) op[r] = 2047 - (int)((unsigned)wm & 0x7FFu);
    }
}

// ---------------- 3) projections q/yk/yv = W @ x (w = blockIdx.z) ----------------
__global__ void k_proj(const float* __restrict__ x) {
    __shared__ float shx[CC*64];   // [c][p]
    __shared__ float shW[CC*CC];   // [cin][cout]
    int b  = blockIdx.y;
    int w  = blockIdx.z;
    int n0 = blockIdx.x * 64;
    int tid = threadIdx.x;
    const float* xb = x + b*CC*NN;
    for (int i = tid; i < CC*64; i += 256) {
        int c = i >> 6, p = i & 63;
        shx[c*64 + p] = xb[c*NN + n0 + p];
    }
    for (int i = tid; i < CC*CC; i += 256) shW[i] = g_WT[w*CC*CC + i];
    __syncthreads();

    int p  = tid & 63;
    int cg = (tid >> 6) << 4;           // 16 output channels per thread
    int bn = b*NN + n0 + p;
    float4 acc[4];
#pragma unroll
    for (int g = 0; g < 4; g++) acc[g] = make_float4(0.f, 0.f, 0.f, 0.f);
#pragma unroll
    for (int k = 0; k < CC; k++) {
        float xv = shx[k*64 + p];
#pragma unroll
        for (int g = 0; g < 4; g++) {
            float4 wv = *(const float4*)&shW[k*CC + cg + g*4];
            acc[g].x = fmaf(xv, wv.x, acc[g].x);
            acc[g].y = fmaf(xv, wv.y, acc[g].y);
            acc[g].z = fmaf(xv, wv.z, acc[g].z);
            acc[g].w = fmaf(xv, wv.w, acc[g].w);
        }
    }
    float* dst = (w == 0 ? g_q : (w == 1 ? g_yk : g_yv)) + bn*CC + cg;
#pragma unroll
    for (int g = 0; g < 4; g++) *(float4*)&dst[g*4] = acc[g];
}

// ---------------- 4) attention (warp per point) + residual -> s1 ----------------
__global__ void k_attn(const float* __restrict__ x) {
    __shared__ float qsh[8][64];
    __shared__ float ykn[8][64];
    __shared__ float att[8][KK*8];
    __shared__ int   nid[8][KK];
    int tid  = threadIdx.x;
    int wid  = tid >> 5, lane = tid & 31;
    int bn   = blockIdx.x * 8 + wid;
    int b    = bn >> 11;
    int n    = bn & (NN - 1);

    qsh[wid][lane]      = g_q [bn*CC + lane];
    qsh[wid][lane + 32] = g_q [bn*CC + lane + 32];
    ykn[wid][lane]      = g_yk[bn*CC + lane];
    ykn[wid][lane + 32] = g_yk[bn*CC + lane + 32];
    int gn = b*NN + g_idx[bn*KK + lane];   // global row of this lane's neighbor
    nid[wid][lane] = gn;
    __syncwarp();

    const float4* kr = (const float4*)&g_yk[gn*CC];
    float e[8];
#pragma unroll
    for (int h = 0; h < 8; h++) e[h] = 0.f;
#pragma unroll
    for (int c4 = 0; c4 < 16; c4++) {
        float4 kv = kr[c4];
        int c = c4*4, h = c4 >> 1;
        float t = (kv.x - ykn[wid][c+0]) * qsh[wid][c+0];
        t = fmaf(kv.y - ykn[wid][c+1], qsh[wid][c+1], t);
        t = fmaf(kv.z - ykn[wid][c+2], qsh[wid][c+2], t);
        t = fmaf(kv.w - ykn[wid][c+3], qsh[wid][c+3], t);
        e[h] += t;
    }
    const float sc = 0.3535533905932738f;  // 1/sqrt(8)
#pragma unroll
    for (int h = 0; h < 8; h++) {
        float eh = e[h] * sc;
        float mx = eh;
#pragma unroll
        for (int o = 16; o > 0; o >>= 1) mx = fmaxf(mx, __shfl_xor_sync(0xffffffffu, mx, o));
        float ex = __expf(eh - mx);
        float sm = ex;
#pragma unroll
        for (int o = 16; o > 0; o >>= 1) sm += __shfl_xor_sync(0xffffffffu, sm, o);
        att[wid][lane*8 + h] = ex / sm;
    }
    __syncwarp();

    // out[c] = sum_j a[j][c>>3]*yv_j[c] - yv_center[c]  (softmax sums to 1)
    float acc0 = 0.f, acc1 = 0.f;
    int h0 = lane >> 3, h1 = (lane >> 3) + 4;
#pragma unroll 4
    for (int j = 0; j < KK; j++) {
        const float* vr = &g_yv[nid[wid][j]*CC];
        acc0 = fmaf(att[wid][j*8 + h0], vr[lane],      acc0);
        acc1 = fmaf(att[wid][j*8 + h1], vr[lane + 32], acc1);
    }
    acc0 -= g_yv[bn*CC + lane];
    acc1 -= g_yv[bn*CC + lane + 32];

    const float* xb = x + b*CC*NN;
    g_s1[bn*CC + lane]      = xb[lane*NN + n]        + acc0;
    g_s1[bn*CC + lane + 32] = xb[(lane + 32)*NN + n] + acc1;
}

// ---------------- 5a/8a) BN stats partials: grid (CC, 16) ----------------
__global__ void k_statsA(int which) {
    const float* s = which ? g_s2 : g_s1;
    int c = blockIdx.x, chunk = blockIdx.y, tid = threadIdx.x;
    int r0 = chunk * 1024;
    float sum = 0.f, sq = 0.f;
#pragma unroll
    for (int r = 0; r < 1024; r += 256) {
        float v = s[(r0 + r + tid)*CC + c];
        sum += v; sq = fmaf(v, v, sq);
    }
    __shared__ float ss[256], s2[256];
    ss[tid] = sum; s2[tid] = sq;
    __syncthreads();
    for (int st = 128; st > 0; st >>= 1) {
        if (tid < st) { ss[tid] += ss[tid + st]; s2[tid] += s2[tid + st]; }
        __syncthreads();
    }
    if (tid == 0) {
        g_ps[which][(c*16 + chunk)*2    ] = ss[0];
        g_ps[which][(c*16 + chunk)*2 + 1] = s2[0];
    }
}

// ---------------- 5b/8b) BN stats finalize ----------------
__global__ void k_statsB(int which) {
    int c = threadIdx.x;
    float sum = 0.f, sq = 0.f;
#pragma unroll
    for (int k = 0; k < 16; k++) {
        sum += g_ps[which][(c*16 + k)*2];
        sq  += g_ps[which][(c*16 + k)*2 + 1];
    }
    float m   = sum * (1.f/BN);
    float var = sq  * (1.f/BN) - m*m;
    float r   = rsqrtf(var + 1e-5f);
    if (which) { g_mean2[c] = m; g_rstd2[c] = r; }
    else       { g_mean1[c] = m; g_rstd1[c] = r; }
}

// ---------------- 6) BN1 + h = lrelu(W1 @ x1); store x1, h ----------------
__global__ void k_ffn1(const float* __restrict__ gg1, const float* __restrict__ bb1) {
    __shared__ float x1sh[CC*32];   // [c][p], 8KB
    __shared__ float Wsh[CC*128];   // [cin][cout], 32KB
    int tid = threadIdx.x;
    int bn0 = blockIdx.x * 32;
    for (int i = tid; i < CC*128; i += 256) Wsh[i] = g_W1T[i];
    for (int i = tid; i < CC*32; i += 256) {
        int c = i >> 5, p = i & 31;
        float v = g_s1[(bn0 + p)*CC + c];
        float x1 = gg1[c]*(v - g_mean1[c])*g_rstd1[c] + bb1[c];
        x1sh[c*32 + p] = x1;
        g_x1[(bn0 + p)*CC + c] = x1;
    }
    __syncthreads();
    int p = tid & 31, og = (tid >> 5) * 16;
    float acc[16];
#pragma unroll
    for (int u = 0; u < 16; u++) acc[u] = 0.f;
#pragma unroll 8
    for (int k = 0; k < CC; k++) {
        float xv = x1sh[k*32 + p];
#pragma unroll
        for (int u = 0; u < 16; u++) acc[u] = fmaf(xv, Wsh[k*128 + og + u], acc[u]);
    }
    float* ho = g_h + (bn0 + p)*128 + og;
#pragma unroll
    for (int u4 = 0; u4 < 4; u4++) {
        float4 o;
        o.x = acc[u4*4+0] > 0.f ? acc[u4*4+0] : 0.2f*acc[u4*4+0];
        o.y = acc[u4*4+1] > 0.f ? acc[u4*4+1] : 0.2f*acc[u4*4+1];
        o.z = acc[u4*4+2] > 0.f ? acc[u4*4+2] : 0.2f*acc[u4*4+2];
        o.w = acc[u4*4+3] > 0.f ? acc[u4*4+3] : 0.2f*acc[u4*4+3];
        *(float4*)&ho[u4*4] = o;
    }
}

// ---------------- 7) s2 = x1 + W2 @ h ----------------
__global__ void k_ffn2() {
    __shared__ float hsh[128*16];   // [k][p], 8KB
    __shared__ float Wsh[128*CC];   // [k][cout], 32KB
    int tid = threadIdx.x;
    int bn0 = blockIdx.x * 16;
    for (int i = tid; i < 128*CC; i += 256) Wsh[i] = g_W2T[i];
    for (int i = tid; i < 128*16; i += 256) {
        int k = i >> 4, p = i & 15;
        hsh[k*16 + p] = g_h[(bn0 + p)*128 + k];
    }
    __syncthreads();
    int p = tid & 15, cg = (tid >> 4) * 4;
    float4 acc = make_float4(0.f, 0.f, 0.f, 0.f);
#pragma unroll 8
    for (int k = 0; k < 128; k++) {
        float hv = hsh[k*16 + p];
        float4 wv = *(const float4*)&Wsh[k*CC + cg];
        acc.x = fmaf(hv, wv.x, acc.x);
        acc.y = fmaf(hv, wv.y, acc.y);
        acc.z = fmaf(hv, wv.z, acc.z);
        acc.w = fmaf(hv, wv.w, acc.w);
    }
    int bn = bn0 + p;
    float4 x1v = *(const float4*)&g_x1[bn*CC + cg];
    float4 o;
    o.x = x1v.x + acc.x; o.y = x1v.y + acc.y;
    o.z = x1v.z + acc.z; o.w = x1v.w + acc.w;
    *(float4*)&g_s2[bn*CC + cg] = o;
}

// ---------------- 9) BN2 + transpose to (B, C, N) output ----------------
__global__ void k_final(const float* __restrict__ gg2, const float* __restrict__ bb2,
                        float* __restrict__ out) {
    int i = blockIdx.x * 256 + threadIdx.x;      // 0 .. B*C*N-1
    int n = i & (NN - 1);
    int c = (i >> 11) & 63;
    int b = i >> 17;
    float v = g_s2[(b*NN + n)*CC + c];
    out[i] = gg2[c]*(v - g_mean2[c])*g_rstd2[c] + bb2[c];
}

// ---------------- launcher ----------------
extern "C" void kernel_launch(void* const* d_in, const int* in_sizes, int n_in,
                              void* d_out, int out_size) {
    const float* x  = (const float*)d_in[0];
    const float* Wq = (const float*)d_in[1];
    const float* Wk = (const float*)d_in[2];
    const float* Wv = (const float*)d_in[3];
    const float* W1 = (const float*)d_in[4];
    const float* W2 = (const float*)d_in[5];
    const float* g1 = (const float*)d_in[6];
    const float* b1 = (const float*)d_in[7];
    const float* g2 = (const float*)d_in[8];
    const float* b2 = (const float*)d_in[9];
    float* out = (float*)d_out;

    k_prep  <<<32, 256>>>(Wq, Wk, Wv, W1, W2);
    k_xx    <<<dim3(NN/256, BB), 256>>>(x);
    k_dist  <<<dim3(NN/128, BB, 4), 128>>>(x);
    k_sel   <<<BN/8, 256>>>();
    k_proj  <<<dim3(NN/64, BB, 3), 256>>>(x);
    k_attn  <<<BN/8, 256>>>(x);
    k_statsA<<<dim3(CC, 16), 256>>>(0);
    k_statsB<<<1, 64>>>(0);
    k_ffn1  <<<BN/32, 256>>>(g1, b1);
    k_ffn2  <<<BN/16, 256>>>();
    k_statsA<<<dim3(CC, 16), 256>>>(1);
    k_statsB<<<1, 64>>>(1);
    k_final <<<(BB*CC*NN)/256, 256>>>(g2, b2, out);
}